// round 15
// baseline (speedup 1.0000x reference)
#include <cuda_runtime.h>
#include <cstdint>

// Problem constants
#define LL 1024
#define DM 768
#define NH 12
#define FD 16
#define HD 64
#define CH 64
#define NC 16
#define DP 288           // padded expanded feature dim (273 -> 288)
#define NW 144           // DP/2 packed words
#define QK_WORDS (64*NW) // 9216 words per (h,c): [row64][nw144]
#define K2_WORDS (DP*32) // 9216 words per (h,c): [n288][iw32]
#define V_WORDS  (64*32) // 2048 words per (h,c): [d64][iw32]
#define S_ELT    (64*DP) // 18432 fp32 per (h,c), layout [d][n]

// Scratch (static device globals)
__device__ float    g_Q[LL*NH*FD];
__device__ float    g_K[LL*NH*FD];
__device__ float    g_V[LL*DM];
__device__ uint32_t g_Qh [NH*NC*QK_WORDS], g_Ql [NH*NC*QK_WORDS]; // Qf packed along n
__device__ uint32_t g_K1h[NH*NC*QK_WORDS], g_K1l[NH*NC*QK_WORDS]; // Kf packed along n (attn B)
__device__ uint32_t g_K2h[NH*NC*K2_WORDS], g_K2l[NH*NC*K2_WORDS]; // Kf packed along i (kv A)
__device__ uint32_t g_Vh [NH*NC*V_WORDS],  g_Vl [NH*NC*V_WORDS];  // V packed along token
__device__ float    g_S  [NH*NC*S_ELT];   // per-chunk KV sums, [d][n]
__device__ float    g_ks [NH*NC*DP];      // per-chunk k-feature sums
__device__ uint32_t g_Sh [NH*NC*QK_WORDS], g_Sl [NH*NC*QK_WORDS]; // prefix S packed: [d][nw]
__device__ uint32_t g_kh [NH*NC*NW],       g_kl [NH*NC*NW];       // prefix ksum packed
__device__ float    g_Y[LL*DM];

// ---------------------------------------------------------------------------
// bf16 split-pack helpers.  x = hi + lo with hi,lo bf16; dropped lo*lo ~2^-18.
// ---------------------------------------------------------------------------
__device__ __forceinline__ void split_pack(float x0, float x1, uint32_t& hi, uint32_t& lo) {
    uint32_t h;
    asm("cvt.rn.bf16x2.f32 %0, %1, %2;" : "=r"(h) : "f"(x1), "f"(x0));  // hi: x1->upper, x0->lower
    float h0 = __uint_as_float(h << 16);
    float h1 = __uint_as_float(h & 0xffff0000u);
    asm("cvt.rn.bf16x2.f32 %0, %1, %2;" : "=r"(lo) : "f"(x1 - h1), "f"(x0 - h0));
    hi = h;
}
__device__ __forceinline__ void mma_bf16(float c[4], const uint32_t a[4], const uint32_t b[2]) {
    asm volatile("mma.sync.aligned.m16n8k16.row.col.f32.bf16.bf16.f32 "
                 "{%0,%1,%2,%3}, {%4,%5,%6,%7}, {%8,%9}, {%0,%1,%2,%3};\n"
                 : "+f"(c[0]), "+f"(c[1]), "+f"(c[2]), "+f"(c[3])
                 : "r"(a[0]), "r"(a[1]), "r"(a[2]), "r"(a[3]),
                   "r"(b[0]), "r"(b[1]));
}
#define ONES2 0x3F803F80u   // (1.0bf16, 1.0bf16)

// ===========================================================================
// 3xBF16 projection GEMM, 64x64 block tile / 128 threads (4 warps, 2x2),
// warp tile 32x32 = 2x4 m16n8k16 subtiles.  (proven round-14 config)
// ===========================================================================
#define GSMBUF 3072                       // words per buffer (Ah/Al/Bh/Bl 768 ea)
#define SMEM_GEMM_BYTES (2 * GSMBUF * 4)  // 24576 B

__device__ __forceinline__ void bf16_body64(const float* __restrict__ A,
                                            const float* __restrict__ B,
                                            float* __restrict__ C,
                                            int N, int K, int bm, int bn,
                                            uint32_t* sm) {
    const int tid  = threadIdx.x, lane = tid & 31, w = tid >> 5;   // 4 warps
    const int wm = w >> 1, wn = w & 1;
    const int gid = lane >> 2, tig = lane & 3;
    const int ar = tid >> 1, aw0 = (tid & 1) * 4;   // A staging: row ar(0..63), words aw0..+3
    const int bnn = tid & 63, bkq = tid >> 6;       // B staging: col bnn, rows bkq*8..+7

    float acc[2][4][4] = {};
    const int nit = K / 16;

    float4 av0 = *(const float4*)&A[(bm + ar) * K + aw0 * 2];
    float4 av1 = *(const float4*)&A[(bm + ar) * K + aw0 * 2 + 4];
    float bv[8];
#pragma unroll
    for (int r = 0; r < 8; r++) bv[r] = B[(bkq * 8 + r) * N + bn + bnn];

    auto cvst = [&](uint32_t* buf, float4 A0, float4 A1, const float* b8) {
        uint32_t* Ah = buf;
        uint32_t* Al = buf + 768;
        uint32_t* Bh = buf + 1536;
        uint32_t* Bl = buf + 2304;
        uint32_t h, l;
        split_pack(A0.x, A0.y, h, l); Ah[ar*12 + aw0 + 0] = h; Al[ar*12 + aw0 + 0] = l;
        split_pack(A0.z, A0.w, h, l); Ah[ar*12 + aw0 + 1] = h; Al[ar*12 + aw0 + 1] = l;
        split_pack(A1.x, A1.y, h, l); Ah[ar*12 + aw0 + 2] = h; Al[ar*12 + aw0 + 2] = l;
        split_pack(A1.z, A1.w, h, l); Ah[ar*12 + aw0 + 3] = h; Al[ar*12 + aw0 + 3] = l;
#pragma unroll
        for (int j = 0; j < 4; j++) {
            split_pack(b8[2*j], b8[2*j+1], h, l);
            Bh[bnn*12 + bkq*4 + j] = h; Bl[bnn*12 + bkq*4 + j] = l;
        }
    };

    cvst(sm, av0, av1, bv);
    __syncthreads();

    for (int it = 0; it < nit; it++) {
        uint32_t* cb = sm + (it & 1) * GSMBUF;
        if (it + 1 < nit) {
            int k0 = (it + 1) * 16;
            av0 = *(const float4*)&A[(bm + ar) * K + k0 + aw0 * 2];
            av1 = *(const float4*)&A[(bm + ar) * K + k0 + aw0 * 2 + 4];
#pragma unroll
            for (int r = 0; r < 8; r++) bv[r] = B[(k0 + bkq * 8 + r) * N + bn + bnn];
        }
        uint32_t* Ah = cb;
        uint32_t* Al = cb + 768;
        uint32_t* Bh = cb + 1536;
        uint32_t* Bl = cb + 2304;
        uint32_t ah[2][4], al_[2][4], bh[4][2], bl_[4][2];
#pragma unroll
        for (int mt = 0; mt < 2; mt++) {
            int rb = wm * 32 + mt * 16;
            ah[mt][0] = Ah[(rb+gid)*12 + tig];     ah[mt][1] = Ah[(rb+gid+8)*12 + tig];
            ah[mt][2] = Ah[(rb+gid)*12 + tig+4];   ah[mt][3] = Ah[(rb+gid+8)*12 + tig+4];
            al_[mt][0] = Al[(rb+gid)*12 + tig];    al_[mt][1] = Al[(rb+gid+8)*12 + tig];
            al_[mt][2] = Al[(rb+gid)*12 + tig+4];  al_[mt][3] = Al[(rb+gid+8)*12 + tig+4];
        }
#pragma unroll
        for (int nt = 0; nt < 4; nt++) {
            int nb = wn * 32 + nt * 8;
            bh[nt][0] = Bh[(nb+gid)*12 + tig];   bh[nt][1] = Bh[(nb+gid)*12 + tig+4];
            bl_[nt][0] = Bl[(nb+gid)*12 + tig];  bl_[nt][1] = Bl[(nb+gid)*12 + tig+4];
        }
#pragma unroll
        for (int mt = 0; mt < 2; mt++)
#pragma unroll
            for (int nt = 0; nt < 4; nt++) {
                mma_bf16(acc[mt][nt], ah[mt],  bh[nt]);
                mma_bf16(acc[mt][nt], ah[mt],  bl_[nt]);
                mma_bf16(acc[mt][nt], al_[mt], bh[nt]);
            }
        if (it + 1 < nit) cvst(sm + ((it + 1) & 1) * GSMBUF, av0, av1, bv);
        __syncthreads();
    }

#pragma unroll
    for (int mt = 0; mt < 2; mt++)
#pragma unroll
        for (int nt = 0; nt < 4; nt++) {
            int row = bm + wm * 32 + mt * 16 + gid;
            int col = bn + wn * 32 + nt * 8 + tig * 2;
            *(float2*)&C[row * N + col]       = make_float2(acc[mt][nt][0], acc[mt][nt][1]);
            *(float2*)&C[(row + 8) * N + col] = make_float2(acc[mt][nt][2], acc[mt][nt][3]);
        }
}

__global__ __launch_bounds__(128) void qkv_gemm(const float* __restrict__ hs,
                                                const float* __restrict__ Wq,
                                                const float* __restrict__ Wk,
                                                const float* __restrict__ Wv) {
    extern __shared__ uint32_t smext[];
    const int bx = blockIdx.x, bm = blockIdx.y * 64;
    const float* B; float* C; int N, bn;
    if (bx < 3)      { B = Wq; C = g_Q; N = NH * FD; bn = bx * 64; }
    else if (bx < 6) { B = Wk; C = g_K; N = NH * FD; bn = (bx - 3) * 64; }
    else             { B = Wv; C = g_V; N = DM;      bn = (bx - 6) * 64; }
    bf16_body64(hs, B, C, N, DM, bm, bn, smext);
}

__global__ __launch_bounds__(128) void o_gemm(const float* __restrict__ Wo,
                                              float* __restrict__ out) {
    extern __shared__ uint32_t smext[];
    bf16_body64(g_Y, Wo, out, DM, DM, blockIdx.y * 64, blockIdx.x * 64, smext);
}

// ===========================================================================
// Featurize + pack.  grid (NC, NH, 4):
//   z=0: Q  -> g_Qh/l  [i][nw]     z=1: K -> g_K1h/l [j][nw]
//   z=2: K  -> g_K2h/l [n][iw]     z=3: V -> g_Vh/l  [d][iw]
// ===========================================================================
__global__ __launch_bounds__(256) void featurize_k() {
    const int c = blockIdx.x, h = blockIdx.y, job = blockIdx.z;
    const int tid = threadIdx.x;

    if (job == 3) {   // V transpose + pack (stride 68: float4-aligned rows)
        __shared__ float vs[64][68];
#pragma unroll
        for (int l = 0; l < 4; l++) {
            int fi = tid + l * 256;
            int i = fi >> 4, d4 = (fi & 15) * 4;
            *(float4*)&vs[i][d4] = *(const float4*)&g_V[(c * CH + i) * DM + h * HD + d4];
        }
        __syncthreads();
        int vb = (h * NC + c) * V_WORDS;
#pragma unroll
        for (int l = 0; l < 8; l++) {
            int wd = tid + l * 256;
            int d = wd >> 5, iw = wd & 31;
            uint32_t hi, lo;
            split_pack(vs[2 * iw][d], vs[2 * iw + 1][d], hi, lo);
            g_Vh[vb + wd] = hi; g_Vl[vb + wd] = lo;
        }
        return;
    }

    __shared__ float xs[64][17];
    const float* __restrict__ src = (job == 0) ? g_Q : g_K;
    for (int idx = tid; idx < CH * FD; idx += 256) {
        int i = idx >> 4, f = idx & 15;
        xs[i][f] = src[(c * CH + i) * (NH * FD) + h * FD + f];
    }
    __syncthreads();
    const float S1 = 0.5f;
    const float S2 = 0.17677669529663687f;
    auto feat = [&](int i, int n) -> float {
        if (n == 0)  return 1.0f;
        if (n <= 16) return xs[i][n - 1] * S1;
        if (n <= 272) { int p = n - 17; return xs[i][p >> 4] * xs[i][p & 15] * S2; }
        return 0.0f;
    };
    const int base = (h * NC + c) * QK_WORDS;
    if (job <= 1) {      // [row i][nw]; incremental i/nw (no div by 144)
        uint32_t* dh = job ? g_K1h : g_Qh;
        uint32_t* dl = job ? g_K1l : g_Ql;
        int i = 0, nw = tid;
        if (nw >= NW) { nw -= NW; i++; }
#pragma unroll 4
        for (int l = 0; l < 36; l++) {
            uint32_t hi, lo;
            split_pack(feat(i, 2 * nw), feat(i, 2 * nw + 1), hi, lo);
            int wd = i * NW + nw;
            dh[base + wd] = hi; dl[base + wd] = lo;
            nw += 256;
            if (nw >= NW) { nw -= NW; i++; }
            if (nw >= NW) { nw -= NW; i++; }
        }
    } else {             // job==2: [n][iw] packed along tokens
#pragma unroll 4
        for (int l = 0; l < 36; l++) {
            int wd = tid + l * 256;
            int n = wd >> 5, iw = wd & 31;
            uint32_t hi, lo;
            split_pack(feat(2 * iw, n), feat(2 * iw + 1, n), hi, lo);
            g_K2h[base + wd] = hi; g_K2l[base + wd] = lo;
        }
    }
}

// ===========================================================================
// chunk_kv (bf16 mma, smem-free): S[d][n] = sum_i Kf[n][i]*V[i][d],
// ksum[n] via ones-B.  grid (2 halves of 144 rows, NC, NH), 288 thr (9 warps).
// ===========================================================================
__global__ __launch_bounds__(288) void chunk_kv_k() {
    const int half = blockIdx.x, c = blockIdx.y, h = blockIdx.z;
    const int tid = threadIdx.x, w = tid >> 5, lane = tid & 31;
    const int gid = lane >> 2, tig = lane & 3;
    const int rbl = half * 144 + w * 16;
    const int kb2 = (h * NC + c) * K2_WORDS;
    const int vb  = (h * NC + c) * V_WORDS;
    float acc[8][4] = {}, acck[4] = {};
    const uint32_t ones[2] = { ONES2, ONES2 };

#pragma unroll
    for (int ks = 0; ks < 4; ks++) {
        const int kw = ks * 8;
        uint32_t ah[4], al_[4];
        ah[0]  = g_K2h[kb2 + (rbl+gid)*32   + kw + tig];
        ah[1]  = g_K2h[kb2 + (rbl+gid+8)*32 + kw + tig];
        ah[2]  = g_K2h[kb2 + (rbl+gid)*32   + kw + tig + 4];
        ah[3]  = g_K2h[kb2 + (rbl+gid+8)*32 + kw + tig + 4];
        al_[0] = g_K2l[kb2 + (rbl+gid)*32   + kw + tig];
        al_[1] = g_K2l[kb2 + (rbl+gid+8)*32 + kw + tig];
        al_[2] = g_K2l[kb2 + (rbl+gid)*32   + kw + tig + 4];
        al_[3] = g_K2l[kb2 + (rbl+gid+8)*32 + kw + tig + 4];
#pragma unroll
        for (int nt = 0; nt < 8; nt++) {
            uint32_t bh[2], bl_[2];
            bh[0]  = g_Vh[vb + (nt*8+gid)*32 + kw + tig];
            bh[1]  = g_Vh[vb + (nt*8+gid)*32 + kw + tig + 4];
            bl_[0] = g_Vl[vb + (nt*8+gid)*32 + kw + tig];
            bl_[1] = g_Vl[vb + (nt*8+gid)*32 + kw + tig + 4];
            mma_bf16(acc[nt], ah,  bh);
            mma_bf16(acc[nt], ah,  bl_);
            mma_bf16(acc[nt], al_, bh);
        }
        mma_bf16(acck, ah,  ones);
        mma_bf16(acck, al_, ones);
    }

    const int sb = (h * NC + c) * S_ELT;
    const int n0 = rbl + gid, n1 = n0 + 8;
#pragma unroll
    for (int nt = 0; nt < 8; nt++) {
        int d0 = nt * 8 + tig * 2;
        g_S[sb + d0 * DP + n0]       = acc[nt][0];
        g_S[sb + (d0 + 1) * DP + n0] = acc[nt][1];
        g_S[sb + d0 * DP + n1]       = acc[nt][2];
        g_S[sb + (d0 + 1) * DP + n1] = acc[nt][3];
    }
    if (tig == 0) {
        g_ks[(h * NC + c) * DP + n0] = acck[0];
        g_ks[(h * NC + c) * DP + n1] = acck[2];
    }
}

// ===========================================================================
// Exclusive prefix over chunks + bf16 pack.  MLP=16 register prefetch.
// ===========================================================================
__global__ __launch_bounds__(256) void prefix_k() {
    const int gid = blockIdx.x * 256 + threadIdx.x;
    const int NSEG = NH * 64 * NW;   // 110592
    if (gid < NSEG) {
        int h = gid / (64 * NW), rem = gid % (64 * NW);
        int d = rem / NW, nw = rem % NW;
        const float* src = g_S + h * NC * S_ELT + d * DP + 2 * nw;
        uint32_t* dh = g_Sh + h * NC * QK_WORDS + d * NW + nw;
        uint32_t* dl = g_Sl + h * NC * QK_WORDS + d * NW + nw;
        float2 v[NC];
#pragma unroll
        for (int c = 0; c < NC; c++) v[c] = *(const float2*)&src[c * S_ELT];
        float a0 = 0.f, a1 = 0.f;
#pragma unroll
        for (int c = 0; c < NC; c++) {
            uint32_t hi, lo;
            split_pack(a0, a1, hi, lo);
            dh[c * QK_WORDS] = hi; dl[c * QK_WORDS] = lo;
            a0 += v[c].x; a1 += v[c].y;
        }
    } else if (gid < NSEG + NH * NW) {
        int j = gid - NSEG;
        int h = j / NW, nw = j % NW;
        const float* src = g_ks + h * NC * DP + 2 * nw;
        uint32_t* dh = g_kh + h * NC * NW + nw;
        uint32_t* dl = g_kl + h * NC * NW + nw;
        float v0[NC], v1[NC];
#pragma unroll
        for (int c = 0; c < NC; c++) { v0[c] = src[c * DP]; v1[c] = src[c * DP + 1]; }
        float a0 = 0.f, a1 = 0.f;
#pragma unroll
        for (int c = 0; c < NC; c++) {
            uint32_t hi, lo;
            split_pack(a0, a1, hi, lo);
            dh[c * NW] = hi; dl[c * NW] = lo;
            a0 += v0[c]; a1 += v1[c];
        }
    }
}

// ===========================================================================
// chunk_attn (bf16, staged smem pipeline, m-split x2): grid (NC, NH, 2),
// 128 thr = 4 warps (wn 0..3), each CTA computes 32 query rows
// (mh*32 .. mh*32+31).  Query rows are fully independent, so the split is
// exact; K/S staged per CTA (L2-shared with the sibling CTA).
// Per-slice buffer: Qh 384 Ql 384 Kh 768 Kl 768 Sh 768 Sl 768 ksh 8 ksl 8.
// ===========================================================================
#define ATTN_BUF 3856
#define ATTN_SMEM ((2 * ATTN_BUF + 2 * 1152 + 32) * 4)   // 40192 B
__global__ __launch_bounds__(128, 4) void chunk_attn_k() {
    extern __shared__ uint32_t usm[];
    uint32_t* bufs = usm;                    // 2 x ATTN_BUF
    uint32_t* Ash  = usm + 2 * ATTN_BUF;     // [32][36] masked scores hi
    uint32_t* Asl  = Ash + 1152;
    float*    den  = (float*)(Asl + 1152);   // [32]

    const int c = blockIdx.x, h = blockIdx.y, mh = blockIdx.z;
    const int tid = threadIdx.x, wn = tid >> 5, lane = tid & 31;
    const int gid = lane >> 2, tig = lane & 3;

    const int qb  = (h * NC + c) * QK_WORDS;
    const int ksb = (h * NC + c) * NW;
    const int vb  = (h * NC + c) * V_WORDS;

    const uint32_t* gQh = g_Qh + qb + mh * 32 * NW;
    const uint32_t* gQl = g_Ql + qb + mh * 32 * NW;
    const uint32_t* gKh = g_K1h + qb;
    const uint32_t* gKl = g_K1l + qb;
    const uint32_t* gSh = g_Sh + qb;
    const uint32_t* gSl = g_Sl + qb;

    const int sr = tid >> 3, skw = tid & 7;     // sr 0..15

    // stage slice 0
    {
#pragma unroll
        for (int hf = 0; hf < 2; hf++) {        // Q: 32 rows
            int r = sr + hf * 16;
            bufs[r * 12 + skw]       = gQh[r * NW + skw];
            bufs[384 + r * 12 + skw] = gQl[r * NW + skw];
        }
#pragma unroll
        for (int hf = 0; hf < 4; hf++) {        // K,S: 64 rows
            int r = sr + hf * 16;
            bufs[768  + r * 12 + skw] = gKh[r * NW + skw];
            bufs[1536 + r * 12 + skw] = gKl[r * NW + skw];
            bufs[2304 + r * 12 + skw] = gSh[r * NW + skw];
            bufs[3072 + r * 12 + skw] = gSl[r * NW + skw];
        }
        if (tid < 8)       bufs[3840 + tid]     = g_kh[ksb + tid];
        else if (tid < 16) bufs[3848 + tid - 8] = g_kl[ksb + tid - 8];
    }
    __syncthreads();

    float aA[2][2][4] = {}, aN[2][2][4] = {}, aD[2][4] = {};
    const uint32_t ones[2] = { ONES2, ONES2 };

    for (int s = 0; s < 18; s++) {
        uint32_t* cb = bufs + (s & 1) * ATTN_BUF;
        uint32_t pfq[4], pfk[16]; uint32_t pks = 0;
        if (s + 1 < 18) {
            const int kw0 = (s + 1) * 8;
#pragma unroll
            for (int hf = 0; hf < 2; hf++) {
                int r = sr + hf * 16;
                pfq[hf * 2 + 0] = gQh[r * NW + kw0 + skw];
                pfq[hf * 2 + 1] = gQl[r * NW + kw0 + skw];
            }
#pragma unroll
            for (int hf = 0; hf < 4; hf++) {
                int r = sr + hf * 16;
                pfk[hf * 4 + 0] = gKh[r * NW + kw0 + skw];
                pfk[hf * 4 + 1] = gKl[r * NW + kw0 + skw];
                pfk[hf * 4 + 2] = gSh[r * NW + kw0 + skw];
                pfk[hf * 4 + 3] = gSl[r * NW + kw0 + skw];
            }
            if (tid < 8)       pks = g_kh[ksb + kw0 + tid];
            else if (tid < 16) pks = g_kl[ksb + kw0 + tid - 8];
        }
        // fragments (scalar LDS, conflict-free via stride 12)
        uint32_t qh[2][4], ql[2][4];
#pragma unroll
        for (int mt = 0; mt < 2; mt++) {
            int rb = mt * 16;
            qh[mt][0] = cb[(rb+gid)*12 + tig];         qh[mt][1] = cb[(rb+gid+8)*12 + tig];
            qh[mt][2] = cb[(rb+gid)*12 + tig+4];       qh[mt][3] = cb[(rb+gid+8)*12 + tig+4];
            ql[mt][0] = cb[384 + (rb+gid)*12 + tig];   ql[mt][1] = cb[384 + (rb+gid+8)*12 + tig];
            ql[mt][2] = cb[384 + (rb+gid)*12 + tig+4]; ql[mt][3] = cb[384 + (rb+gid+8)*12 + tig+4];
        }
        uint32_t kh[2][2], kl_[2][2], sh[2][2], sl_[2][2];
#pragma unroll
        for (int nt = 0; nt < 2; nt++) {
            int cbn = wn * 16 + nt * 8;
            kh[nt][0]  = cb[768  + (cbn+gid)*12 + tig]; kh[nt][1]  = cb[768  + (cbn+gid)*12 + tig+4];
            kl_[nt][0] = cb[1536 + (cbn+gid)*12 + tig]; kl_[nt][1] = cb[1536 + (cbn+gid)*12 + tig+4];
            sh[nt][0]  = cb[2304 + (cbn+gid)*12 + tig]; sh[nt][1]  = cb[2304 + (cbn+gid)*12 + tig+4];
            sl_[nt][0] = cb[3072 + (cbn+gid)*12 + tig]; sl_[nt][1] = cb[3072 + (cbn+gid)*12 + tig+4];
        }
#pragma unroll
        for (int mt = 0; mt < 2; mt++)
#pragma unroll
            for (int nt = 0; nt < 2; nt++) {
                mma_bf16(aA[mt][nt], qh[mt], kh[nt]);
                mma_bf16(aA[mt][nt], qh[mt], kl_[nt]);
                mma_bf16(aA[mt][nt], ql[mt], kh[nt]);
                mma_bf16(aN[mt][nt], qh[mt], sh[nt]);
                mma_bf16(aN[mt][nt], qh[mt], sl_[nt]);
                mma_bf16(aN[mt][nt], ql[mt], sh[nt]);
            }
        if (wn == 0) {
            uint32_t bh2[2] = { cb[3840 + tig], cb[3840 + tig + 4] };
            uint32_t bl2[2] = { cb[3848 + tig], cb[3848 + tig + 4] };
#pragma unroll
            for (int mt = 0; mt < 2; mt++) {
                mma_bf16(aD[mt], qh[mt], bh2);
                mma_bf16(aD[mt], qh[mt], bl2);
                mma_bf16(aD[mt], ql[mt], bh2);
            }
        }
        if (s + 1 < 18) {
            uint32_t* nb2 = bufs + ((s + 1) & 1) * ATTN_BUF;
#pragma unroll
            for (int hf = 0; hf < 2; hf++) {
                int r = sr + hf * 16;
                nb2[r * 12 + skw]       = pfq[hf * 2 + 0];
                nb2[384 + r * 12 + skw] = pfq[hf * 2 + 1];
            }
#pragma unroll
            for (int hf = 0; hf < 4; hf++) {
                int r = sr + hf * 16;
                nb2[768  + r * 12 + skw] = pfk[hf * 4 + 0];
                nb2[1536 + r * 12 + skw] = pfk[hf * 4 + 1];
                nb2[2304 + r * 12 + skw] = pfk[hf * 4 + 2];
                nb2[3072 + r * 12 + skw] = pfk[hf * 4 + 3];
            }
            if (tid < 8)       nb2[3840 + tid]     = pks;
            else if (tid < 16) nb2[3848 + tid - 8] = pks;
        }
        __syncthreads();
    }

    // mask scores (keep j <= global row), pack, stash to smem (local rows 0..31)
#pragma unroll
    for (int mt = 0; mt < 2; mt++)
#pragma unroll
        for (int nt = 0; nt < 2; nt++) {
            int ri0 = mt * 16 + gid, ri1 = ri0 + 8;       // local
            int gr0 = mh * 32 + ri0, gr1 = gr0 + 8;       // global query row
            int j0 = wn * 16 + nt * 8 + tig * 2;
            int jw = wn * 8 + nt * 4 + tig;
            float x0 = (j0     <= gr0) ? aA[mt][nt][0] : 0.f;
            float x1 = (j0 + 1 <= gr0) ? aA[mt][nt][1] : 0.f;
            float x2 = (j0     <= gr1) ? aA[mt][nt][2] : 0.f;
            float x3 = (j0 + 1 <= gr1) ? aA[mt][nt][3] : 0.f;
            uint32_t hi, lo;
            split_pack(x0, x1, hi, lo); Ash[ri0 * 36 + jw] = hi; Asl[ri0 * 36 + jw] = lo;
            split_pack(x2, x3, hi, lo); Ash[ri1 * 36 + jw] = hi; Asl[ri1 * 36 + jw] = lo;
        }
    __syncthreads();

    // phase 2: num += A @ V ; den += rowsum(A)
#pragma unroll
    for (int ks = 0; ks < 4; ks++) {
        const int kw = ks * 8;
        uint32_t ah[2][4], al2[2][4];
#pragma unroll
        for (int mt = 0; mt < 2; mt++) {
            int rb = mt * 16;
            ah[mt][0]  = Ash[(rb+gid)*36 + kw + tig];   ah[mt][1]  = Ash[(rb+gid+8)*36 + kw + tig];
            ah[mt][2]  = Ash[(rb+gid)*36 + kw + tig+4]; ah[mt][3]  = Ash[(rb+gid+8)*36 + kw + tig+4];
            al2[mt][0] = Asl[(rb+gid)*36 + kw + tig];   al2[mt][1] = Asl[(rb+gid+8)*36 + kw + tig];
            al2[mt][2] = Asl[(rb+gid)*36 + kw + tig+4]; al2[mt][3] = Asl[(rb+gid+8)*36 + kw + tig+4];
        }
#pragma unroll
        for (int nt = 0; nt < 2; nt++) {
            int d = wn * 16 + nt * 8 + gid;
            uint32_t bh2[2] = { g_Vh[vb + d*32 + kw + tig], g_Vh[vb + d*32 + kw + tig + 4] };
            uint32_t bl2[2] = { g_Vl[vb + d*32 + kw + tig], g_Vl[vb + d*32 + kw + tig + 4] };
#pragma unroll
            for (int mt = 0; mt < 2; mt++) {
                mma_bf16(aN[mt][nt], ah[mt],  bh2);
                mma_bf16(aN[mt][nt], ah[mt],  bl2);
                mma_bf16(aN[mt][nt], al2[mt], bh2);
            }
        }
        if (wn == 0) {
#pragma unroll
            for (int mt = 0; mt < 2; mt++) {
                mma_bf16(aD[mt], ah[mt],  ones);
                mma_bf16(aD[mt], al2[mt], ones);
            }
        }
    }
    if (wn == 0 && tig == 0) {
#pragma unroll
        for (int mt = 0; mt < 2; mt++) {
            den[mt * 16 + gid]     = aD[mt][0];
            den[mt * 16 + gid + 8] = aD[mt][2];
        }
    }
    __syncthreads();

    // divide & store
#pragma unroll
    for (int mt = 0; mt < 2; mt++) {
        int ri0 = mt * 16 + gid, ri1 = ri0 + 8;
        int gr0 = mh * 32 + ri0, gr1 = gr0 + 8;
        float inv0 = 1.0f / (den[ri0] + 1e-12f);
        float inv1 = 1.0f / (den[ri1] + 1e-12f);
#pragma unroll
        for (int nt = 0; nt < 2; nt++) {
            int cb0 = wn * 16 + nt * 8 + tig * 2;
            *(float2*)&g_Y[(c * CH + gr0) * DM + h * HD + cb0] =
                make_float2(aN[mt][nt][0] * inv0, aN[mt][nt][1] * inv0);
            *(float2*)&g_Y[(c * CH + gr1) * DM + h * HD + cb0] =
                make_float2(aN[mt][nt][2] * inv1, aN[mt][nt][3] * inv1);
        }
    }
}

// ---------------------------------------------------------------------------
extern "C" void kernel_launch(void* const* d_in, const int* in_sizes, int n_in,
                              void* d_out, int out_size) {
    const float* hs = (const float*)d_in[0];
    const float* Wq = (const float*)d_in[1];
    const float* Wk = (const float*)d_in[2];
    const float* Wv = (const float*)d_in[3];
    const float* Wo = (const float*)d_in[4];
    float* out = (float*)d_out;

    cudaFuncSetAttribute(chunk_attn_k, cudaFuncAttributeMaxDynamicSharedMemorySize, ATTN_SMEM);
    cudaFuncSetAttribute(qkv_gemm, cudaFuncAttributeMaxDynamicSharedMemorySize, SMEM_GEMM_BYTES);
    cudaFuncSetAttribute(o_gemm,   cudaFuncAttributeMaxDynamicSharedMemorySize, SMEM_GEMM_BYTES);

    qkv_gemm<<<dim3(18, 16), 128, SMEM_GEMM_BYTES>>>(hs, Wq, Wk, Wv);
    featurize_k<<<dim3(NC, NH, 4), 256>>>();
    chunk_kv_k<<<dim3(2, NC, NH), 288>>>();
    {
        int total = NH * 64 * NW + NH * NW;   // 112320
        prefix_k<<<(total + 255) / 256, 256>>>();
    }
    chunk_attn_k<<<dim3(NC, NH, 2), 128, ATTN_SMEM>>>();
    o_gemm<<<dim3(12, 16), 128, SMEM_GEMM_BYTES>>>(Wo, out);
}

// round 16
// speedup vs baseline: 1.1285x; 1.1285x over previous
#include <cuda_runtime.h>
#include <cstdint>

// Problem constants
#define LL 1024
#define DM 768
#define NH 12
#define FD 16
#define HD 64
#define CH 64
#define NC 16
#define DP 288           // padded expanded feature dim (273 -> 288)
#define NW 144           // DP/2 packed words
#define QK_WORDS (64*NW) // 9216 words per (h,c): [row64][nw144]
#define K2_WORDS (DP*32) // 9216 words per (h,c): [n288][iw32]
#define V_WORDS  (64*32) // 2048 words per (h,c): [d64][iw32]
#define S_ELT    (64*DP) // 18432 fp32 per (h,c), layout [d][n]

// Scratch (static device globals)
__device__ float    g_Q[LL*NH*FD];
__device__ float    g_K[LL*NH*FD];
__device__ float    g_V[LL*DM];
__device__ uint32_t g_Qh [NH*NC*QK_WORDS], g_Ql [NH*NC*QK_WORDS]; // Qf packed along n
__device__ uint32_t g_K1h[NH*NC*QK_WORDS], g_K1l[NH*NC*QK_WORDS]; // Kf packed along n (attn B)
__device__ uint32_t g_K2h[NH*NC*K2_WORDS], g_K2l[NH*NC*K2_WORDS]; // Kf packed along i (kv A)
__device__ uint32_t g_Vh [NH*NC*V_WORDS],  g_Vl [NH*NC*V_WORDS];  // V packed along token
__device__ float    g_S  [NH*NC*S_ELT];   // per-chunk KV sums, [d][n]
__device__ float    g_ks [NH*NC*DP];      // per-chunk k-feature sums
__device__ uint32_t g_Sh [NH*NC*QK_WORDS], g_Sl [NH*NC*QK_WORDS]; // prefix S packed: [d][nw]
__device__ uint32_t g_kh [NH*NC*NW],       g_kl [NH*NC*NW];       // prefix ksum packed
__device__ float    g_Y[LL*DM];

// ---------------------------------------------------------------------------
// bf16 split-pack helpers.  x = hi + lo with hi,lo bf16; dropped lo*lo ~2^-18.
// ---------------------------------------------------------------------------
__device__ __forceinline__ void split_pack(float x0, float x1, uint32_t& hi, uint32_t& lo) {
    uint32_t h;
    asm("cvt.rn.bf16x2.f32 %0, %1, %2;" : "=r"(h) : "f"(x1), "f"(x0));  // hi: x1->upper, x0->lower
    float h0 = __uint_as_float(h << 16);
    float h1 = __uint_as_float(h & 0xffff0000u);
    asm("cvt.rn.bf16x2.f32 %0, %1, %2;" : "=r"(lo) : "f"(x1 - h1), "f"(x0 - h0));
    hi = h;
}
__device__ __forceinline__ void mma_bf16(float c[4], const uint32_t a[4], const uint32_t b[2]) {
    asm volatile("mma.sync.aligned.m16n8k16.row.col.f32.bf16.bf16.f32 "
                 "{%0,%1,%2,%3}, {%4,%5,%6,%7}, {%8,%9}, {%0,%1,%2,%3};\n"
                 : "+f"(c[0]), "+f"(c[1]), "+f"(c[2]), "+f"(c[3])
                 : "r"(a[0]), "r"(a[1]), "r"(a[2]), "r"(a[3]),
                   "r"(b[0]), "r"(b[1]));
}
#define ONES2 0x3F803F80u   // (1.0bf16, 1.0bf16)

// ===========================================================================
// 3xBF16 projection GEMM, 64x64 block tile / 128 threads (4 warps, 2x2),
// warp tile 32x32 = 2x4 m16n8k16 subtiles, BK=32 (24 stages, 48 mma/stage
// per warp, half the syncs of the BK=16 version).  smem stride 20 words:
// fragment LDS addr = 20*gid + kw + tig spans 32 distinct banks.
// ===========================================================================
#define GSMBUF 5120                       // words/buffer: Ah/Al/Bh/Bl 1280 each
#define SMEM_GEMM_BYTES (2 * GSMBUF * 4)  // 40960 B

__device__ __forceinline__ void bf16_body64(const float* __restrict__ A,
                                            const float* __restrict__ B,
                                            float* __restrict__ C,
                                            int N, int K, int bm, int bn,
                                            uint32_t* sm) {
    const int tid  = threadIdx.x, lane = tid & 31, w = tid >> 5;   // 4 warps
    const int wm = w >> 1, wn = w & 1;
    const int gid = lane >> 2, tig = lane & 3;
    const int ar = tid >> 1, aw0 = (tid & 1) * 8;   // A staging: row ar, words aw0..+7
    const int bnn = tid & 63, bkq = tid >> 6;       // B staging: col bnn, words bkq*8..+7

    float acc[2][4][4] = {};
    const int nit = K / 32;                         // 24 stages

    float4 av[4];
#pragma unroll
    for (int j = 0; j < 4; j++)
        av[j] = *(const float4*)&A[(bm + ar) * K + aw0 * 2 + j * 4];
    float bv[16];
#pragma unroll
    for (int r = 0; r < 16; r++) bv[r] = B[(bkq * 16 + r) * N + bn + bnn];

    auto cvst = [&](uint32_t* buf, const float4* a4, const float* b16) {
        uint32_t* Ah = buf;
        uint32_t* Al = buf + 1280;
        uint32_t* Bh = buf + 2560;
        uint32_t* Bl = buf + 3840;
        uint32_t h, l;
#pragma unroll
        for (int j = 0; j < 4; j++) {
            split_pack(a4[j].x, a4[j].y, h, l);
            Ah[ar*20 + aw0 + 2*j]     = h; Al[ar*20 + aw0 + 2*j]     = l;
            split_pack(a4[j].z, a4[j].w, h, l);
            Ah[ar*20 + aw0 + 2*j + 1] = h; Al[ar*20 + aw0 + 2*j + 1] = l;
        }
#pragma unroll
        for (int j = 0; j < 8; j++) {
            split_pack(b16[2*j], b16[2*j+1], h, l);
            Bh[bnn*20 + bkq*8 + j] = h; Bl[bnn*20 + bkq*8 + j] = l;
        }
    };

    cvst(sm, av, bv);
    __syncthreads();

    for (int it = 0; it < nit; it++) {
        uint32_t* cb = sm + (it & 1) * GSMBUF;
        if (it + 1 < nit) {
            int k0 = (it + 1) * 32;
#pragma unroll
            for (int j = 0; j < 4; j++)
                av[j] = *(const float4*)&A[(bm + ar) * K + k0 + aw0 * 2 + j * 4];
#pragma unroll
            for (int r = 0; r < 16; r++) bv[r] = B[(k0 + bkq * 16 + r) * N + bn + bnn];
        }
        uint32_t* Ah = cb;
        uint32_t* Al = cb + 1280;
        uint32_t* Bh = cb + 2560;
        uint32_t* Bl = cb + 3840;
#pragma unroll
        for (int ks = 0; ks < 2; ks++) {
            const int kw = ks * 8;
            uint32_t ah[2][4], al_[2][4], bh[4][2], bl_[4][2];
#pragma unroll
            for (int mt = 0; mt < 2; mt++) {
                int rb = wm * 32 + mt * 16;
                ah[mt][0] = Ah[(rb+gid)*20 + kw + tig];     ah[mt][1] = Ah[(rb+gid+8)*20 + kw + tig];
                ah[mt][2] = Ah[(rb+gid)*20 + kw + tig+4];   ah[mt][3] = Ah[(rb+gid+8)*20 + kw + tig+4];
                al_[mt][0] = Al[(rb+gid)*20 + kw + tig];    al_[mt][1] = Al[(rb+gid+8)*20 + kw + tig];
                al_[mt][2] = Al[(rb+gid)*20 + kw + tig+4];  al_[mt][3] = Al[(rb+gid+8)*20 + kw + tig+4];
            }
#pragma unroll
            for (int nt = 0; nt < 4; nt++) {
                int nb = wn * 32 + nt * 8;
                bh[nt][0] = Bh[(nb+gid)*20 + kw + tig];   bh[nt][1] = Bh[(nb+gid)*20 + kw + tig+4];
                bl_[nt][0] = Bl[(nb+gid)*20 + kw + tig];  bl_[nt][1] = Bl[(nb+gid)*20 + kw + tig+4];
            }
#pragma unroll
            for (int mt = 0; mt < 2; mt++)
#pragma unroll
                for (int nt = 0; nt < 4; nt++) {
                    mma_bf16(acc[mt][nt], ah[mt],  bh[nt]);
                    mma_bf16(acc[mt][nt], ah[mt],  bl_[nt]);
                    mma_bf16(acc[mt][nt], al_[mt], bh[nt]);
                }
        }
        if (it + 1 < nit) cvst(sm + ((it + 1) & 1) * GSMBUF, av, bv);
        __syncthreads();
    }

#pragma unroll
    for (int mt = 0; mt < 2; mt++)
#pragma unroll
        for (int nt = 0; nt < 4; nt++) {
            int row = bm + wm * 32 + mt * 16 + gid;
            int col = bn + wn * 32 + nt * 8 + tig * 2;
            *(float2*)&C[row * N + col]       = make_float2(acc[mt][nt][0], acc[mt][nt][1]);
            *(float2*)&C[(row + 8) * N + col] = make_float2(acc[mt][nt][2], acc[mt][nt][3]);
        }
}

__global__ __launch_bounds__(128) void qkv_gemm(const float* __restrict__ hs,
                                                const float* __restrict__ Wq,
                                                const float* __restrict__ Wk,
                                                const float* __restrict__ Wv) {
    extern __shared__ uint32_t smext[];
    const int bx = blockIdx.x, bm = blockIdx.y * 64;
    const float* B; float* C; int N, bn;
    if (bx < 3)      { B = Wq; C = g_Q; N = NH * FD; bn = bx * 64; }
    else if (bx < 6) { B = Wk; C = g_K; N = NH * FD; bn = (bx - 3) * 64; }
    else             { B = Wv; C = g_V; N = DM;      bn = (bx - 6) * 64; }
    bf16_body64(hs, B, C, N, DM, bm, bn, smext);
}

__global__ __launch_bounds__(128) void o_gemm(const float* __restrict__ Wo,
                                              float* __restrict__ out) {
    extern __shared__ uint32_t smext[];
    bf16_body64(g_Y, Wo, out, DM, DM, blockIdx.y * 64, blockIdx.x * 64, smext);
}

// ===========================================================================
// Featurize + pack.  grid (NC, NH, 4):
//   z=0: Q  -> g_Qh/l  [i][nw]     z=1: K -> g_K1h/l [j][nw]
//   z=2: K  -> g_K2h/l [n][iw]     z=3: V -> g_Vh/l  [d][iw]
// ===========================================================================
__global__ __launch_bounds__(256) void featurize_k() {
    const int c = blockIdx.x, h = blockIdx.y, job = blockIdx.z;
    const int tid = threadIdx.x;

    if (job == 3) {   // V transpose + pack (stride 68: float4-aligned rows)
        __shared__ float vs[64][68];
#pragma unroll
        for (int l = 0; l < 4; l++) {
            int fi = tid + l * 256;
            int i = fi >> 4, d4 = (fi & 15) * 4;
            *(float4*)&vs[i][d4] = *(const float4*)&g_V[(c * CH + i) * DM + h * HD + d4];
        }
        __syncthreads();
        int vb = (h * NC + c) * V_WORDS;
#pragma unroll
        for (int l = 0; l < 8; l++) {
            int wd = tid + l * 256;
            int d = wd >> 5, iw = wd & 31;
            uint32_t hi, lo;
            split_pack(vs[2 * iw][d], vs[2 * iw + 1][d], hi, lo);
            g_Vh[vb + wd] = hi; g_Vl[vb + wd] = lo;
        }
        return;
    }

    __shared__ float xs[64][17];
    const float* __restrict__ src = (job == 0) ? g_Q : g_K;
    for (int idx = tid; idx < CH * FD; idx += 256) {
        int i = idx >> 4, f = idx & 15;
        xs[i][f] = src[(c * CH + i) * (NH * FD) + h * FD + f];
    }
    __syncthreads();
    const float S1 = 0.5f;
    const float S2 = 0.17677669529663687f;
    auto feat = [&](int i, int n) -> float {
        if (n == 0)  return 1.0f;
        if (n <= 16) return xs[i][n - 1] * S1;
        if (n <= 272) { int p = n - 17; return xs[i][p >> 4] * xs[i][p & 15] * S2; }
        return 0.0f;
    };
    const int base = (h * NC + c) * QK_WORDS;
    if (job <= 1) {      // [row i][nw]; incremental i/nw (no div by 144)
        uint32_t* dh = job ? g_K1h : g_Qh;
        uint32_t* dl = job ? g_K1l : g_Ql;
        int i = 0, nw = tid;
        if (nw >= NW) { nw -= NW; i++; }
#pragma unroll 4
        for (int l = 0; l < 36; l++) {
            uint32_t hi, lo;
            split_pack(feat(i, 2 * nw), feat(i, 2 * nw + 1), hi, lo);
            int wd = i * NW + nw;
            dh[base + wd] = hi; dl[base + wd] = lo;
            nw += 256;
            if (nw >= NW) { nw -= NW; i++; }
            if (nw >= NW) { nw -= NW; i++; }
        }
    } else {             // job==2: [n][iw] packed along tokens
#pragma unroll 4
        for (int l = 0; l < 36; l++) {
            int wd = tid + l * 256;
            int n = wd >> 5, iw = wd & 31;
            uint32_t hi, lo;
            split_pack(feat(2 * iw, n), feat(2 * iw + 1, n), hi, lo);
            g_K2h[base + wd] = hi; g_K2l[base + wd] = lo;
        }
    }
}

// ===========================================================================
// chunk_kv (bf16 mma, smem-free): S[d][n] = sum_i Kf[n][i]*V[i][d],
// ksum[n] via ones-B.  grid (2 halves of 144 rows, NC, NH), 288 thr (9 warps).
// ===========================================================================
__global__ __launch_bounds__(288) void chunk_kv_k() {
    const int half = blockIdx.x, c = blockIdx.y, h = blockIdx.z;
    const int tid = threadIdx.x, w = tid >> 5, lane = tid & 31;
    const int gid = lane >> 2, tig = lane & 3;
    const int rbl = half * 144 + w * 16;
    const int kb2 = (h * NC + c) * K2_WORDS;
    const int vb  = (h * NC + c) * V_WORDS;
    float acc[8][4] = {}, acck[4] = {};
    const uint32_t ones[2] = { ONES2, ONES2 };

#pragma unroll
    for (int ks = 0; ks < 4; ks++) {
        const int kw = ks * 8;
        uint32_t ah[4], al_[4];
        ah[0]  = g_K2h[kb2 + (rbl+gid)*32   + kw + tig];
        ah[1]  = g_K2h[kb2 + (rbl+gid+8)*32 + kw + tig];
        ah[2]  = g_K2h[kb2 + (rbl+gid)*32   + kw + tig + 4];
        ah[3]  = g_K2h[kb2 + (rbl+gid+8)*32 + kw + tig + 4];
        al_[0] = g_K2l[kb2 + (rbl+gid)*32   + kw + tig];
        al_[1] = g_K2l[kb2 + (rbl+gid+8)*32 + kw + tig];
        al_[2] = g_K2l[kb2 + (rbl+gid)*32   + kw + tig + 4];
        al_[3] = g_K2l[kb2 + (rbl+gid+8)*32 + kw + tig + 4];
#pragma unroll
        for (int nt = 0; nt < 8; nt++) {
            uint32_t bh[2], bl_[2];
            bh[0]  = g_Vh[vb + (nt*8+gid)*32 + kw + tig];
            bh[1]  = g_Vh[vb + (nt*8+gid)*32 + kw + tig + 4];
            bl_[0] = g_Vl[vb + (nt*8+gid)*32 + kw + tig];
            bl_[1] = g_Vl[vb + (nt*8+gid)*32 + kw + tig + 4];
            mma_bf16(acc[nt], ah,  bh);
            mma_bf16(acc[nt], ah,  bl_);
            mma_bf16(acc[nt], al_, bh);
        }
        mma_bf16(acck, ah,  ones);
        mma_bf16(acck, al_, ones);
    }

    const int sb = (h * NC + c) * S_ELT;
    const int n0 = rbl + gid, n1 = n0 + 8;
#pragma unroll
    for (int nt = 0; nt < 8; nt++) {
        int d0 = nt * 8 + tig * 2;
        g_S[sb + d0 * DP + n0]       = acc[nt][0];
        g_S[sb + (d0 + 1) * DP + n0] = acc[nt][1];
        g_S[sb + d0 * DP + n1]       = acc[nt][2];
        g_S[sb + (d0 + 1) * DP + n1] = acc[nt][3];
    }
    if (tig == 0) {
        g_ks[(h * NC + c) * DP + n0] = acck[0];
        g_ks[(h * NC + c) * DP + n1] = acck[2];
    }
}

// ===========================================================================
// Exclusive prefix over chunks + bf16 pack.  MLP=16 register prefetch.
// ===========================================================================
__global__ __launch_bounds__(256) void prefix_k() {
    const int gid = blockIdx.x * 256 + threadIdx.x;
    const int NSEG = NH * 64 * NW;   // 110592
    if (gid < NSEG) {
        int h = gid / (64 * NW), rem = gid % (64 * NW);
        int d = rem / NW, nw = rem % NW;
        const float* src = g_S + h * NC * S_ELT + d * DP + 2 * nw;
        uint32_t* dh = g_Sh + h * NC * QK_WORDS + d * NW + nw;
        uint32_t* dl = g_Sl + h * NC * QK_WORDS + d * NW + nw;
        float2 v[NC];
#pragma unroll
        for (int c = 0; c < NC; c++) v[c] = *(const float2*)&src[c * S_ELT];
        float a0 = 0.f, a1 = 0.f;
#pragma unroll
        for (int c = 0; c < NC; c++) {
            uint32_t hi, lo;
            split_pack(a0, a1, hi, lo);
            dh[c * QK_WORDS] = hi; dl[c * QK_WORDS] = lo;
            a0 += v[c].x; a1 += v[c].y;
        }
    } else if (gid < NSEG + NH * NW) {
        int j = gid - NSEG;
        int h = j / NW, nw = j % NW;
        const float* src = g_ks + h * NC * DP + 2 * nw;
        uint32_t* dh = g_kh + h * NC * NW + nw;
        uint32_t* dl = g_kl + h * NC * NW + nw;
        float v0[NC], v1[NC];
#pragma unroll
        for (int c = 0; c < NC; c++) { v0[c] = src[c * DP]; v1[c] = src[c * DP + 1]; }
        float a0 = 0.f, a1 = 0.f;
#pragma unroll
        for (int c = 0; c < NC; c++) {
            uint32_t hi, lo;
            split_pack(a0, a1, hi, lo);
            dh[c * NW] = hi; dl[c * NW] = lo;
            a0 += v0[c]; a1 += v1[c];
        }
    }
}

// ===========================================================================
// chunk_attn (bf16, staged smem pipeline, scalar LDS fragments — proven
// round-12 configuration): per (c,h) block, 256 thr, 8 warps (wm 2 x wn 4).
// ===========================================================================
#define ATTN_BUF 4624   // words: Qh 768 Ql 768 Kh 768 Kl 768 Sh 768 Sl 768 ksh 8 ksl 8
#define ATTN_SMEM ((2 * ATTN_BUF + 2 * 2304 + 64) * 4)   // 55680 B
__global__ __launch_bounds__(256, 2) void chunk_attn_k() {
    extern __shared__ uint32_t usm[];
    uint32_t* bufs = usm;                    // 2 x ATTN_BUF
    uint32_t* Ash  = usm + 2 * ATTN_BUF;     // [i][jw] stride 36
    uint32_t* Asl  = Ash + 2304;
    float*    den  = (float*)(Asl + 2304);   // [64]

    const int c = blockIdx.x, h = blockIdx.y;
    const int tid = threadIdx.x, w = tid >> 5, lane = tid & 31;
    const int wm = w >> 2, wn = w & 3;
    const int gid = lane >> 2, tig = lane & 3;

    const int qb  = (h * NC + c) * QK_WORDS;
    const int ksb = (h * NC + c) * NW;
    const int vb  = (h * NC + c) * V_WORDS;

    const uint32_t* gsrc[6] = { g_Qh + qb, g_Ql + qb, g_K1h + qb,
                                g_K1l + qb, g_Sh + qb, g_Sl + qb };
    const int sr = tid >> 3, skw = tid & 7;     // staging coords

    // stage slice 0
    {
#pragma unroll
        for (int o = 0; o < 6; o++)
#pragma unroll
            for (int hf = 0; hf < 2; hf++) {
                int r = sr + hf * 32;
                bufs[o * 768 + r * 12 + skw] = gsrc[o][r * NW + skw];
            }
        if (tid < 8)       bufs[4608 + tid]     = g_kh[ksb + tid];
        else if (tid < 16) bufs[4616 + tid - 8] = g_kl[ksb + tid - 8];
    }
    __syncthreads();

    float aA[2][2][4] = {}, aN[2][2][4] = {}, aD[2][4] = {};
    const uint32_t ones[2] = { ONES2, ONES2 };

    for (int s = 0; s < 18; s++) {
        uint32_t* cb = bufs + (s & 1) * ATTN_BUF;
        uint32_t pf[12]; uint32_t pks = 0;
        if (s + 1 < 18) {
            const int kw0 = (s + 1) * 8;
#pragma unroll
            for (int o = 0; o < 6; o++)
#pragma unroll
                for (int hf = 0; hf < 2; hf++) {
                    int r = sr + hf * 32;
                    pf[o * 2 + hf] = gsrc[o][r * NW + kw0 + skw];
                }
            if (tid < 8)       pks = g_kh[ksb + kw0 + tid];
            else if (tid < 16) pks = g_kl[ksb + kw0 + tid - 8];
        }
        // fragments (scalar LDS, conflict-free via stride 12)
        uint32_t qh[2][4], ql[2][4];
#pragma unroll
        for (int mt = 0; mt < 2; mt++) {
            int rb = wm * 32 + mt * 16;
            qh[mt][0] = cb[(rb+gid)*12 + tig];         qh[mt][1] = cb[(rb+gid+8)*12 + tig];
            qh[mt][2] = cb[(rb+gid)*12 + tig+4];       qh[mt][3] = cb[(rb+gid+8)*12 + tig+4];
            ql[mt][0] = cb[768 + (rb+gid)*12 + tig];   ql[mt][1] = cb[768 + (rb+gid+8)*12 + tig];
            ql[mt][2] = cb[768 + (rb+gid)*12 + tig+4]; ql[mt][3] = cb[768 + (rb+gid+8)*12 + tig+4];
        }
        uint32_t kh[2][2], kl_[2][2], sh[2][2], sl_[2][2];
#pragma unroll
        for (int nt = 0; nt < 2; nt++) {
            int cbn = wn * 16 + nt * 8;
            kh[nt][0]  = cb[1536 + (cbn+gid)*12 + tig]; kh[nt][1]  = cb[1536 + (cbn+gid)*12 + tig+4];
            kl_[nt][0] = cb[2304 + (cbn+gid)*12 + tig]; kl_[nt][1] = cb[2304 + (cbn+gid)*12 + tig+4];
            sh[nt][0]  = cb[3072 + (cbn+gid)*12 + tig]; sh[nt][1]  = cb[3072 + (cbn+gid)*12 + tig+4];
            sl_[nt][0] = cb[3840 + (cbn+gid)*12 + tig]; sl_[nt][1] = cb[3840 + (cbn+gid)*12 + tig+4];
        }
#pragma unroll
        for (int mt = 0; mt < 2; mt++)
#pragma unroll
            for (int nt = 0; nt < 2; nt++) {
                mma_bf16(aA[mt][nt], qh[mt], kh[nt]);
                mma_bf16(aA[mt][nt], qh[mt], kl_[nt]);
                mma_bf16(aA[mt][nt], ql[mt], kh[nt]);
                mma_bf16(aN[mt][nt], qh[mt], sh[nt]);
                mma_bf16(aN[mt][nt], qh[mt], sl_[nt]);
                mma_bf16(aN[mt][nt], ql[mt], sh[nt]);
            }
        if (wn == 0) {
            uint32_t bh2[2] = { cb[4608 + tig], cb[4608 + tig + 4] };
            uint32_t bl2[2] = { cb[4616 + tig], cb[4616 + tig + 4] };
#pragma unroll
            for (int mt = 0; mt < 2; mt++) {
                mma_bf16(aD[mt], qh[mt], bh2);
                mma_bf16(aD[mt], qh[mt], bl2);
                mma_bf16(aD[mt], ql[mt], bh2);
            }
        }
        if (s + 1 < 18) {
            uint32_t* nb2 = bufs + ((s + 1) & 1) * ATTN_BUF;
#pragma unroll
            for (int o = 0; o < 6; o++)
#pragma unroll
                for (int hf = 0; hf < 2; hf++) {
                    int r = sr + hf * 32;
                    nb2[o * 768 + r * 12 + skw] = pf[o * 2 + hf];
                }
            if (tid < 8)       nb2[4608 + tid]     = pks;
            else if (tid < 16) nb2[4616 + tid - 8] = pks;
        }
        __syncthreads();
    }

    // mask scores (keep j <= i), pack, stash to smem
#pragma unroll
    for (int mt = 0; mt < 2; mt++)
#pragma unroll
        for (int nt = 0; nt < 2; nt++) {
            int ri0 = wm * 32 + mt * 16 + gid, ri1 = ri0 + 8;
            int j0 = wn * 16 + nt * 8 + tig * 2;
            int jw = wn * 8 + nt * 4 + tig;
            float x0 = (j0     <= ri0) ? aA[mt][nt][0] : 0.f;
            float x1 = (j0 + 1 <= ri0) ? aA[mt][nt][1] : 0.f;
            float x2 = (j0     <= ri1) ? aA[mt][nt][2] : 0.f;
            float x3 = (j0 + 1 <= ri1) ? aA[mt][nt][3] : 0.f;
            uint32_t hi, lo;
            split_pack(x0, x1, hi, lo); Ash[ri0 * 36 + jw] = hi; Asl[ri0 * 36 + jw] = lo;
            split_pack(x2, x3, hi, lo); Ash[ri1 * 36 + jw] = hi; Asl[ri1 * 36 + jw] = lo;
        }
    __syncthreads();

    // phase 2: num += A @ V ; den += rowsum(A)
#pragma unroll
    for (int ks = 0; ks < 4; ks++) {
        const int kw = ks * 8;
        uint32_t ah[2][4], al2[2][4];
#pragma unroll
        for (int mt = 0; mt < 2; mt++) {
            int rb = wm * 32 + mt * 16;
            ah[mt][0]  = Ash[(rb+gid)*36 + kw + tig];   ah[mt][1]  = Ash[(rb+gid+8)*36 + kw + tig];
            ah[mt][2]  = Ash[(rb+gid)*36 + kw + tig+4]; ah[mt][3]  = Ash[(rb+gid+8)*36 + kw + tig+4];
            al2[mt][0] = Asl[(rb+gid)*36 + kw + tig];   al2[mt][1] = Asl[(rb+gid+8)*36 + kw + tig];
            al2[mt][2] = Asl[(rb+gid)*36 + kw + tig+4]; al2[mt][3] = Asl[(rb+gid+8)*36 + kw + tig+4];
        }
#pragma unroll
        for (int nt = 0; nt < 2; nt++) {
            int d = wn * 16 + nt * 8 + gid;
            uint32_t bh2[2] = { g_Vh[vb + d*32 + kw + tig], g_Vh[vb + d*32 + kw + tig + 4] };
            uint32_t bl2[2] = { g_Vl[vb + d*32 + kw + tig], g_Vl[vb + d*32 + kw + tig + 4] };
#pragma unroll
            for (int mt = 0; mt < 2; mt++) {
                mma_bf16(aN[mt][nt], ah[mt],  bh2);
                mma_bf16(aN[mt][nt], ah[mt],  bl2);
                mma_bf16(aN[mt][nt], al2[mt], bh2);
            }
        }
        if (wn == 0) {
#pragma unroll
            for (int mt = 0; mt < 2; mt++) {
                mma_bf16(aD[mt], ah[mt],  ones);
                mma_bf16(aD[mt], al2[mt], ones);
            }
        }
    }
    if (wn == 0 && tig == 0) {
#pragma unroll
        for (int mt = 0; mt < 2; mt++) {
            den[wm * 32 + mt * 16 + gid]     = aD[mt][0];
            den[wm * 32 + mt * 16 + gid + 8] = aD[mt][2];
        }
    }
    __syncthreads();

    // divide & store
#pragma unroll
    for (int mt = 0; mt < 2; mt++) {
        int ri0 = wm * 32 + mt * 16 + gid, ri1 = ri0 + 8;
        float inv0 = 1.0f / (den[ri0] + 1e-12f);
        float inv1 = 1.0f / (den[ri1] + 1e-12f);
#pragma unroll
        for (int nt = 0; nt < 2; nt++) {
            int cb0 = wn * 16 + nt * 8 + tig * 2;
            *(float2*)&g_Y[(c * CH + ri0) * DM + h * HD + cb0] =
                make_float2(aN[mt][nt][0] * inv0, aN[mt][nt][1] * inv0);
            *(float2*)&g_Y[(c * CH + ri1) * DM + h * HD + cb0] =
                make_float2(aN[mt][nt][2] * inv1, aN[mt][nt][3] * inv1);
        }
    }
}

// ---------------------------------------------------------------------------
extern "C" void kernel_launch(void* const* d_in, const int* in_sizes, int n_in,
                              void* d_out, int out_size) {
    const float* hs = (const float*)d_in[0];
    const float* Wq = (const float*)d_in[1];
    const float* Wk = (const float*)d_in[2];
    const float* Wv = (const float*)d_in[3];
    const float* Wo = (const float*)d_in[4];
    float* out = (float*)d_out;

    cudaFuncSetAttribute(chunk_attn_k, cudaFuncAttributeMaxDynamicSharedMemorySize, ATTN_SMEM);
    cudaFuncSetAttribute(qkv_gemm, cudaFuncAttributeMaxDynamicSharedMemorySize, SMEM_GEMM_BYTES);
    cudaFuncSetAttribute(o_gemm,   cudaFuncAttributeMaxDynamicSharedMemorySize, SMEM_GEMM_BYTES);

    qkv_gemm<<<dim3(18, 16), 128, SMEM_GEMM_BYTES>>>(hs, Wq, Wk, Wv);
    featurize_k<<<dim3(NC, NH, 4), 256>>>();
    chunk_kv_k<<<dim3(2, NC, NH), 288>>>();
    {
        int total = NH * 64 * NW + NH * NW;   // 112320
        prefix_k<<<(total + 255) / 256, 256>>>();
    }
    chunk_attn_k<<<dim3(NC, NH), 256, ATTN_SMEM>>>();
    o_gemm<<<dim3(12, 16), 128, SMEM_GEMM_BYTES>>>(Wo, out);
}

// round 17
// speedup vs baseline: 1.1651x; 1.0324x over previous
#include <cuda_runtime.h>
#include <cstdint>

// Problem constants
#define LL 1024
#define DM 768
#define NH 12
#define FD 16
#define HD 64
#define CH 64
#define NC 16
#define DP 288           // padded expanded feature dim (273 -> 288)
#define NW 144           // DP/2 packed words
#define QK_WORDS (64*NW) // 9216 words per (h,c): [row64][nw144]
#define K2_WORDS (DP*32) // 9216 words per (h,c): [n288][iw32]
#define V_WORDS  (64*32) // 2048 words per (h,c): [d64][iw32]
#define S_ELT    (64*DP) // 18432 fp32 per (h,c), layout [d][n]

// Scratch (static device globals)
__device__ float    g_Q[LL*NH*FD];
__device__ float    g_K[LL*NH*FD];
__device__ float    g_V[LL*DM];
__device__ uint32_t g_Qh [NH*NC*QK_WORDS], g_Ql [NH*NC*QK_WORDS]; // Qf packed along n
__device__ uint32_t g_K1h[NH*NC*QK_WORDS], g_K1l[NH*NC*QK_WORDS]; // Kf packed along n (attn B)
__device__ uint32_t g_K2h[NH*NC*K2_WORDS], g_K2l[NH*NC*K2_WORDS]; // Kf packed along i (kv A)
__device__ uint32_t g_Vh [NH*NC*V_WORDS],  g_Vl [NH*NC*V_WORDS];  // V packed along token
__device__ float    g_S  [NH*NC*S_ELT];   // per-chunk KV sums, [d][n]
__device__ float    g_ks [NH*NC*DP];      // per-chunk k-feature sums
__device__ uint32_t g_Sh [NH*NC*QK_WORDS], g_Sl [NH*NC*QK_WORDS]; // prefix S packed: [d][nw]
__device__ uint32_t g_kh [NH*NC*NW],       g_kl [NH*NC*NW];       // prefix ksum packed
__device__ float    g_Y[LL*DM];

// ---------------------------------------------------------------------------
// bf16 split-pack helpers.  x = hi + lo with hi,lo bf16; dropped lo*lo ~2^-18.
// ---------------------------------------------------------------------------
__device__ __forceinline__ void split_pack(float x0, float x1, uint32_t& hi, uint32_t& lo) {
    uint32_t h;
    asm("cvt.rn.bf16x2.f32 %0, %1, %2;" : "=r"(h) : "f"(x1), "f"(x0));  // hi: x1->upper, x0->lower
    float h0 = __uint_as_float(h << 16);
    float h1 = __uint_as_float(h & 0xffff0000u);
    asm("cvt.rn.bf16x2.f32 %0, %1, %2;" : "=r"(lo) : "f"(x1 - h1), "f"(x0 - h0));
    hi = h;
}
__device__ __forceinline__ void mma_bf16(float c[4], const uint32_t a[4], const uint32_t b[2]) {
    asm volatile("mma.sync.aligned.m16n8k16.row.col.f32.bf16.bf16.f32 "
                 "{%0,%1,%2,%3}, {%4,%5,%6,%7}, {%8,%9}, {%0,%1,%2,%3};\n"
                 : "+f"(c[0]), "+f"(c[1]), "+f"(c[2]), "+f"(c[3])
                 : "r"(a[0]), "r"(a[1]), "r"(a[2]), "r"(a[3]),
                   "r"(b[0]), "r"(b[1]));
}
__device__ __forceinline__ uint32_t sptr(const void* p) {
    return (uint32_t)__cvta_generic_to_shared(p);
}
__device__ __forceinline__ void cp_async8(uint32_t saddr, const void* g) {
    asm volatile("cp.async.ca.shared.global [%0], [%1], 8;" :: "r"(saddr), "l"(g) : "memory");
}
__device__ __forceinline__ void cp_async16(uint32_t saddr, const void* g) {
    asm volatile("cp.async.cg.shared.global [%0], [%1], 16;" :: "r"(saddr), "l"(g) : "memory");
}
__device__ __forceinline__ void cp_commit() {
    asm volatile("cp.async.commit_group;" ::: "memory");
}
#define ONES2 0x3F803F80u   // (1.0bf16, 1.0bf16)

// ===========================================================================
// 3xBF16 projection GEMM, 64x64 block tile / 128 threads (4 warps, 2x2),
// warp tile 32x32 = 2x4 m16n8k16 subtiles, BK=32 (24 stages).
// (proven round-16 configuration)
// ===========================================================================
#define GSMBUF 5120                       // words/buffer: Ah/Al/Bh/Bl 1280 each
#define SMEM_GEMM_BYTES (2 * GSMBUF * 4)  // 40960 B

__device__ __forceinline__ void bf16_body64(const float* __restrict__ A,
                                            const float* __restrict__ B,
                                            float* __restrict__ C,
                                            int N, int K, int bm, int bn,
                                            uint32_t* sm) {
    const int tid  = threadIdx.x, lane = tid & 31, w = tid >> 5;   // 4 warps
    const int wm = w >> 1, wn = w & 1;
    const int gid = lane >> 2, tig = lane & 3;
    const int ar = tid >> 1, aw0 = (tid & 1) * 8;   // A staging: row ar, words aw0..+7
    const int bnn = tid & 63, bkq = tid >> 6;       // B staging: col bnn, words bkq*8..+7

    float acc[2][4][4] = {};
    const int nit = K / 32;                         // 24 stages

    float4 av[4];
#pragma unroll
    for (int j = 0; j < 4; j++)
        av[j] = *(const float4*)&A[(bm + ar) * K + aw0 * 2 + j * 4];
    float bv[16];
#pragma unroll
    for (int r = 0; r < 16; r++) bv[r] = B[(bkq * 16 + r) * N + bn + bnn];

    auto cvst = [&](uint32_t* buf, const float4* a4, const float* b16) {
        uint32_t* Ah = buf;
        uint32_t* Al = buf + 1280;
        uint32_t* Bh = buf + 2560;
        uint32_t* Bl = buf + 3840;
        uint32_t h, l;
#pragma unroll
        for (int j = 0; j < 4; j++) {
            split_pack(a4[j].x, a4[j].y, h, l);
            Ah[ar*20 + aw0 + 2*j]     = h; Al[ar*20 + aw0 + 2*j]     = l;
            split_pack(a4[j].z, a4[j].w, h, l);
            Ah[ar*20 + aw0 + 2*j + 1] = h; Al[ar*20 + aw0 + 2*j + 1] = l;
        }
#pragma unroll
        for (int j = 0; j < 8; j++) {
            split_pack(b16[2*j], b16[2*j+1], h, l);
            Bh[bnn*20 + bkq*8 + j] = h; Bl[bnn*20 + bkq*8 + j] = l;
        }
    };

    cvst(sm, av, bv);
    __syncthreads();

    for (int it = 0; it < nit; it++) {
        uint32_t* cb = sm + (it & 1) * GSMBUF;
        if (it + 1 < nit) {
            int k0 = (it + 1) * 32;
#pragma unroll
            for (int j = 0; j < 4; j++)
                av[j] = *(const float4*)&A[(bm + ar) * K + k0 + aw0 * 2 + j * 4];
#pragma unroll
            for (int r = 0; r < 16; r++) bv[r] = B[(k0 + bkq * 16 + r) * N + bn + bnn];
        }
        uint32_t* Ah = cb;
        uint32_t* Al = cb + 1280;
        uint32_t* Bh = cb + 2560;
        uint32_t* Bl = cb + 3840;
#pragma unroll
        for (int ks = 0; ks < 2; ks++) {
            const int kw = ks * 8;
            uint32_t ah[2][4], al_[2][4], bh[4][2], bl_[4][2];
#pragma unroll
            for (int mt = 0; mt < 2; mt++) {
                int rb = wm * 32 + mt * 16;
                ah[mt][0] = Ah[(rb+gid)*20 + kw + tig];     ah[mt][1] = Ah[(rb+gid+8)*20 + kw + tig];
                ah[mt][2] = Ah[(rb+gid)*20 + kw + tig+4];   ah[mt][3] = Ah[(rb+gid+8)*20 + kw + tig+4];
                al_[mt][0] = Al[(rb+gid)*20 + kw + tig];    al_[mt][1] = Al[(rb+gid+8)*20 + kw + tig];
                al_[mt][2] = Al[(rb+gid)*20 + kw + tig+4];  al_[mt][3] = Al[(rb+gid+8)*20 + kw + tig+4];
            }
#pragma unroll
            for (int nt = 0; nt < 4; nt++) {
                int nb = wn * 32 + nt * 8;
                bh[nt][0] = Bh[(nb+gid)*20 + kw + tig];   bh[nt][1] = Bh[(nb+gid)*20 + kw + tig+4];
                bl_[nt][0] = Bl[(nb+gid)*20 + kw + tig];  bl_[nt][1] = Bl[(nb+gid)*20 + kw + tig+4];
            }
#pragma unroll
            for (int mt = 0; mt < 2; mt++)
#pragma unroll
                for (int nt = 0; nt < 4; nt++) {
                    mma_bf16(acc[mt][nt], ah[mt],  bh[nt]);
                    mma_bf16(acc[mt][nt], ah[mt],  bl_[nt]);
                    mma_bf16(acc[mt][nt], al_[mt], bh[nt]);
                }
        }
        if (it + 1 < nit) cvst(sm + ((it + 1) & 1) * GSMBUF, av, bv);
        __syncthreads();
    }

#pragma unroll
    for (int mt = 0; mt < 2; mt++)
#pragma unroll
        for (int nt = 0; nt < 4; nt++) {
            int row = bm + wm * 32 + mt * 16 + gid;
            int col = bn + wn * 32 + nt * 8 + tig * 2;
            *(float2*)&C[row * N + col]       = make_float2(acc[mt][nt][0], acc[mt][nt][1]);
            *(float2*)&C[(row + 8) * N + col] = make_float2(acc[mt][nt][2], acc[mt][nt][3]);
        }
}

__global__ __launch_bounds__(128) void qkv_gemm(const float* __restrict__ hs,
                                                const float* __restrict__ Wq,
                                                const float* __restrict__ Wk,
                                                const float* __restrict__ Wv) {
    extern __shared__ uint32_t smext[];
    const int bx = blockIdx.x, bm = blockIdx.y * 64;
    const float* B; float* C; int N, bn;
    if (bx < 3)      { B = Wq; C = g_Q; N = NH * FD; bn = bx * 64; }
    else if (bx < 6) { B = Wk; C = g_K; N = NH * FD; bn = (bx - 3) * 64; }
    else             { B = Wv; C = g_V; N = DM;      bn = (bx - 6) * 64; }
    bf16_body64(hs, B, C, N, DM, bm, bn, smext);
}

__global__ __launch_bounds__(128) void o_gemm(const float* __restrict__ Wo,
                                              float* __restrict__ out) {
    extern __shared__ uint32_t smext[];
    bf16_body64(g_Y, Wo, out, DM, DM, blockIdx.y * 64, blockIdx.x * 64, smext);
}

// ===========================================================================
// Featurize + pack.  grid (NC, NH, 4):
//   z=0: Q  -> g_Qh/l  [i][nw]     z=1: K -> g_K1h/l [j][nw]
//   z=2: K  -> g_K2h/l [n][iw]     z=3: V -> g_Vh/l  [d][iw]
// ===========================================================================
__global__ __launch_bounds__(256) void featurize_k() {
    const int c = blockIdx.x, h = blockIdx.y, job = blockIdx.z;
    const int tid = threadIdx.x;

    if (job == 3) {   // V transpose + pack (stride 68: float4-aligned rows)
        __shared__ float vs[64][68];
#pragma unroll
        for (int l = 0; l < 4; l++) {
            int fi = tid + l * 256;
            int i = fi >> 4, d4 = (fi & 15) * 4;
            *(float4*)&vs[i][d4] = *(const float4*)&g_V[(c * CH + i) * DM + h * HD + d4];
        }
        __syncthreads();
        int vb = (h * NC + c) * V_WORDS;
#pragma unroll
        for (int l = 0; l < 8; l++) {
            int wd = tid + l * 256;
            int d = wd >> 5, iw = wd & 31;
            uint32_t hi, lo;
            split_pack(vs[2 * iw][d], vs[2 * iw + 1][d], hi, lo);
            g_Vh[vb + wd] = hi; g_Vl[vb + wd] = lo;
        }
        return;
    }

    __shared__ float xs[64][17];
    const float* __restrict__ src = (job == 0) ? g_Q : g_K;
    for (int idx = tid; idx < CH * FD; idx += 256) {
        int i = idx >> 4, f = idx & 15;
        xs[i][f] = src[(c * CH + i) * (NH * FD) + h * FD + f];
    }
    __syncthreads();
    const float S1 = 0.5f;
    const float S2 = 0.17677669529663687f;
    auto feat = [&](int i, int n) -> float {
        if (n == 0)  return 1.0f;
        if (n <= 16) return xs[i][n - 1] * S1;
        if (n <= 272) { int p = n - 17; return xs[i][p >> 4] * xs[i][p & 15] * S2; }
        return 0.0f;
    };
    const int base = (h * NC + c) * QK_WORDS;
    if (job <= 1) {      // [row i][nw]; incremental i/nw (no div by 144)
        uint32_t* dh = job ? g_K1h : g_Qh;
        uint32_t* dl = job ? g_K1l : g_Ql;
        int i = 0, nw = tid;
        if (nw >= NW) { nw -= NW; i++; }
#pragma unroll 4
        for (int l = 0; l < 36; l++) {
            uint32_t hi, lo;
            split_pack(feat(i, 2 * nw), feat(i, 2 * nw + 1), hi, lo);
            int wd = i * NW + nw;
            dh[base + wd] = hi; dl[base + wd] = lo;
            nw += 256;
            if (nw >= NW) { nw -= NW; i++; }
            if (nw >= NW) { nw -= NW; i++; }
        }
    } else {             // job==2: [n][iw] packed along tokens
#pragma unroll 4
        for (int l = 0; l < 36; l++) {
            int wd = tid + l * 256;
            int n = wd >> 5, iw = wd & 31;
            uint32_t hi, lo;
            split_pack(feat(2 * iw, n), feat(2 * iw + 1, n), hi, lo);
            g_K2h[base + wd] = hi; g_K2l[base + wd] = lo;
        }
    }
}

// ===========================================================================
// chunk_kv (bf16 mma, smem-free): S[d][n] = sum_i Kf[n][i]*V[i][d],
// ksum[n] via ones-B.  grid (2 halves of 144 rows, NC, NH), 288 thr (9 warps).
// ===========================================================================
__global__ __launch_bounds__(288) void chunk_kv_k() {
    const int half = blockIdx.x, c = blockIdx.y, h = blockIdx.z;
    const int tid = threadIdx.x, w = tid >> 5, lane = tid & 31;
    const int gid = lane >> 2, tig = lane & 3;
    const int rbl = half * 144 + w * 16;
    const int kb2 = (h * NC + c) * K2_WORDS;
    const int vb  = (h * NC + c) * V_WORDS;
    float acc[8][4] = {}, acck[4] = {};
    const uint32_t ones[2] = { ONES2, ONES2 };

#pragma unroll
    for (int ks = 0; ks < 4; ks++) {
        const int kw = ks * 8;
        uint32_t ah[4], al_[4];
        ah[0]  = g_K2h[kb2 + (rbl+gid)*32   + kw + tig];
        ah[1]  = g_K2h[kb2 + (rbl+gid+8)*32 + kw + tig];
        ah[2]  = g_K2h[kb2 + (rbl+gid)*32   + kw + tig + 4];
        ah[3]  = g_K2h[kb2 + (rbl+gid+8)*32 + kw + tig + 4];
        al_[0] = g_K2l[kb2 + (rbl+gid)*32   + kw + tig];
        al_[1] = g_K2l[kb2 + (rbl+gid+8)*32 + kw + tig];
        al_[2] = g_K2l[kb2 + (rbl+gid)*32   + kw + tig + 4];
        al_[3] = g_K2l[kb2 + (rbl+gid+8)*32 + kw + tig + 4];
#pragma unroll
        for (int nt = 0; nt < 8; nt++) {
            uint32_t bh[2], bl_[2];
            bh[0]  = g_Vh[vb + (nt*8+gid)*32 + kw + tig];
            bh[1]  = g_Vh[vb + (nt*8+gid)*32 + kw + tig + 4];
            bl_[0] = g_Vl[vb + (nt*8+gid)*32 + kw + tig];
            bl_[1] = g_Vl[vb + (nt*8+gid)*32 + kw + tig + 4];
            mma_bf16(acc[nt], ah,  bh);
            mma_bf16(acc[nt], ah,  bl_);
            mma_bf16(acc[nt], al_, bh);
        }
        mma_bf16(acck, ah,  ones);
        mma_bf16(acck, al_, ones);
    }

    const int sb = (h * NC + c) * S_ELT;
    const int n0 = rbl + gid, n1 = n0 + 8;
#pragma unroll
    for (int nt = 0; nt < 8; nt++) {
        int d0 = nt * 8 + tig * 2;
        g_S[sb + d0 * DP + n0]       = acc[nt][0];
        g_S[sb + (d0 + 1) * DP + n0] = acc[nt][1];
        g_S[sb + d0 * DP + n1]       = acc[nt][2];
        g_S[sb + (d0 + 1) * DP + n1] = acc[nt][3];
    }
    if (tig == 0) {
        g_ks[(h * NC + c) * DP + n0] = acck[0];
        g_ks[(h * NC + c) * DP + n1] = acck[2];
    }
}

// ===========================================================================
// Exclusive prefix over chunks + bf16 pack.  MLP=16 register prefetch.
// ===========================================================================
__global__ __launch_bounds__(256) void prefix_k() {
    const int gid = blockIdx.x * 256 + threadIdx.x;
    const int NSEG = NH * 64 * NW;   // 110592
    if (gid < NSEG) {
        int h = gid / (64 * NW), rem = gid % (64 * NW);
        int d = rem / NW, nw = rem % NW;
        const float* src = g_S + h * NC * S_ELT + d * DP + 2 * nw;
        uint32_t* dh = g_Sh + h * NC * QK_WORDS + d * NW + nw;
        uint32_t* dl = g_Sl + h * NC * QK_WORDS + d * NW + nw;
        float2 v[NC];
#pragma unroll
        for (int c = 0; c < NC; c++) v[c] = *(const float2*)&src[c * S_ELT];
        float a0 = 0.f, a1 = 0.f;
#pragma unroll
        for (int c = 0; c < NC; c++) {
            uint32_t hi, lo;
            split_pack(a0, a1, hi, lo);
            dh[c * QK_WORDS] = hi; dl[c * QK_WORDS] = lo;
            a0 += v[c].x; a1 += v[c].y;
        }
    } else if (gid < NSEG + NH * NW) {
        int j = gid - NSEG;
        int h = j / NW, nw = j % NW;
        const float* src = g_ks + h * NC * DP + 2 * nw;
        uint32_t* dh = g_kh + h * NC * NW + nw;
        uint32_t* dl = g_kl + h * NC * NW + nw;
        float v0[NC], v1[NC];
#pragma unroll
        for (int c = 0; c < NC; c++) { v0[c] = src[c * DP]; v1[c] = src[c * DP + 1]; }
        float a0 = 0.f, a1 = 0.f;
#pragma unroll
        for (int c = 0; c < NC; c++) {
            uint32_t hi, lo;
            split_pack(a0, a1, hi, lo);
            dh[c * NW] = hi; dl[c * NW] = lo;
            a0 += v0[c]; a1 += v1[c];
        }
    }
}

// ===========================================================================
// chunk_attn: bf16 mma, cp.async 3-buffer ring staging (no prefetch
// registers, no store phase, 1 barrier/stage).  per (c,h) block, 256 thr,
// 8 warps (wm 2 x wn 4).  Buffer layout per stage (stride-12 rows):
// Qh 0 Ql 768 Kh 1536 Kl 2304 Sh 3072 Sl 3840 ksh 4608(8) ksl 4616(8).
// ===========================================================================
#define ATTN_BUF 4624
#define ATTN_SMEM ((3 * ATTN_BUF + 2 * 2304 + 64) * 4)   // 74176 B
__global__ __launch_bounds__(256, 2) void chunk_attn_k() {
    extern __shared__ uint32_t usm[];
    uint32_t* bufs = usm;                    // 3 x ATTN_BUF ring
    uint32_t* Ash  = usm + 3 * ATTN_BUF;     // [i][jw] stride 36
    uint32_t* Asl  = Ash + 2304;
    float*    den  = (float*)(Asl + 2304);   // [64]

    const int c = blockIdx.x, h = blockIdx.y;
    const int tid = threadIdx.x, w = tid >> 5, lane = tid & 31;
    const int wm = w >> 2, wn = w & 3;
    const int gid = lane >> 2, tig = lane & 3;

    const int qb  = (h * NC + c) * QK_WORDS;
    const int ksb = (h * NC + c) * NW;
    const int vb  = (h * NC + c) * V_WORDS;

    const uint32_t* gsrc[6] = { g_Qh + qb, g_Ql + qb, g_K1h + qb,
                                g_K1l + qb, g_Sh + qb, g_Sl + qb };
    const int r_ = tid >> 2, w2 = (tid & 3) * 2;   // staging: row, word pair

    // cp.async one 8-word slice s into ring buffer bi
    auto stage = [&](int s, int bi) {
        const int kw0 = s * 8;
        const uint32_t sb_ = sptr(bufs + bi * ATTN_BUF);
#pragma unroll
        for (int o = 0; o < 6; o++)
            cp_async8(sb_ + (uint32_t)(o * 768 + r_ * 12 + w2) * 4,
                      gsrc[o] + r_ * NW + kw0 + w2);
        if (tid < 2)      cp_async16(sb_ + (uint32_t)(4608 + tid * 4) * 4,
                                     g_kh + ksb + kw0 + tid * 4);
        else if (tid < 4) cp_async16(sb_ + (uint32_t)(4616 + (tid - 2) * 4) * 4,
                                     g_kl + ksb + kw0 + (tid - 2) * 4);
    };

    stage(0, 0);
    cp_commit();

    float aA[2][2][4] = {}, aN[2][2][4] = {}, aD[2][4] = {};
    const uint32_t ones[2] = { ONES2, ONES2 };

    for (int s = 0; s < 18; s++) {
        const int bi = s % 3;
        if (s + 1 < 18) {
            stage(s + 1, (s + 1) % 3);
            cp_commit();
            asm volatile("cp.async.wait_group 1;" ::: "memory");
        } else {
            asm volatile("cp.async.wait_group 0;" ::: "memory");
        }
        __syncthreads();

        uint32_t* cb = bufs + bi * ATTN_BUF;
        // fragments (scalar LDS, conflict-free via stride 12)
        uint32_t qh[2][4], ql[2][4];
#pragma unroll
        for (int mt = 0; mt < 2; mt++) {
            int rb = wm * 32 + mt * 16;
            qh[mt][0] = cb[(rb+gid)*12 + tig];         qh[mt][1] = cb[(rb+gid+8)*12 + tig];
            qh[mt][2] = cb[(rb+gid)*12 + tig+4];       qh[mt][3] = cb[(rb+gid+8)*12 + tig+4];
            ql[mt][0] = cb[768 + (rb+gid)*12 + tig];   ql[mt][1] = cb[768 + (rb+gid+8)*12 + tig];
            ql[mt][2] = cb[768 + (rb+gid)*12 + tig+4]; ql[mt][3] = cb[768 + (rb+gid+8)*12 + tig+4];
        }
        uint32_t kh[2][2], kl_[2][2], sh[2][2], sl_[2][2];
#pragma unroll
        for (int nt = 0; nt < 2; nt++) {
            int cbn = wn * 16 + nt * 8;
            kh[nt][0]  = cb[1536 + (cbn+gid)*12 + tig]; kh[nt][1]  = cb[1536 + (cbn+gid)*12 + tig+4];
            kl_[nt][0] = cb[2304 + (cbn+gid)*12 + tig]; kl_[nt][1] = cb[2304 + (cbn+gid)*12 + tig+4];
            sh[nt][0]  = cb[3072 + (cbn+gid)*12 + tig]; sh[nt][1]  = cb[3072 + (cbn+gid)*12 + tig+4];
            sl_[nt][0] = cb[3840 + (cbn+gid)*12 + tig]; sl_[nt][1] = cb[3840 + (cbn+gid)*12 + tig+4];
        }
#pragma unroll
        for (int mt = 0; mt < 2; mt++)
#pragma unroll
            for (int nt = 0; nt < 2; nt++) {
                mma_bf16(aA[mt][nt], qh[mt], kh[nt]);
                mma_bf16(aA[mt][nt], qh[mt], kl_[nt]);
                mma_bf16(aA[mt][nt], ql[mt], kh[nt]);
                mma_bf16(aN[mt][nt], qh[mt], sh[nt]);
                mma_bf16(aN[mt][nt], qh[mt], sl_[nt]);
                mma_bf16(aN[mt][nt], ql[mt], sh[nt]);
            }
        if (wn == 0) {
            uint32_t bh2[2] = { cb[4608 + tig], cb[4608 + tig + 4] };
            uint32_t bl2[2] = { cb[4616 + tig], cb[4616 + tig + 4] };
#pragma unroll
            for (int mt = 0; mt < 2; mt++) {
                mma_bf16(aD[mt], qh[mt], bh2);
                mma_bf16(aD[mt], qh[mt], bl2);
                mma_bf16(aD[mt], ql[mt], bh2);
            }
        }
    }

    // mask scores (keep j <= i), pack, stash to smem
#pragma unroll
    for (int mt = 0; mt < 2; mt++)
#pragma unroll
        for (int nt = 0; nt < 2; nt++) {
            int ri0 = wm * 32 + mt * 16 + gid, ri1 = ri0 + 8;
            int j0 = wn * 16 + nt * 8 + tig * 2;
            int jw = wn * 8 + nt * 4 + tig;
            float x0 = (j0     <= ri0) ? aA[mt][nt][0] : 0.f;
            float x1 = (j0 + 1 <= ri0) ? aA[mt][nt][1] : 0.f;
            float x2 = (j0     <= ri1) ? aA[mt][nt][2] : 0.f;
            float x3 = (j0 + 1 <= ri1) ? aA[mt][nt][3] : 0.f;
            uint32_t hi, lo;
            split_pack(x0, x1, hi, lo); Ash[ri0 * 36 + jw] = hi; Asl[ri0 * 36 + jw] = lo;
            split_pack(x2, x3, hi, lo); Ash[ri1 * 36 + jw] = hi; Asl[ri1 * 36 + jw] = lo;
        }
    __syncthreads();

    // phase 2: num += A @ V ; den += rowsum(A)
#pragma unroll
    for (int ks = 0; ks < 4; ks++) {
        const int kw = ks * 8;
        uint32_t ah[2][4], al2[2][4];
#pragma unroll
        for (int mt = 0; mt < 2; mt++) {
            int rb = wm * 32 + mt * 16;
            ah[mt][0]  = Ash[(rb+gid)*36 + kw + tig];   ah[mt][1]  = Ash[(rb+gid+8)*36 + kw + tig];
            ah[mt][2]  = Ash[(rb+gid)*36 + kw + tig+4]; ah[mt][3]  = Ash[(rb+gid+8)*36 + kw + tig+4];
            al2[mt][0] = Asl[(rb+gid)*36 + kw + tig];   al2[mt][1] = Asl[(rb+gid+8)*36 + kw + tig];
            al2[mt][2] = Asl[(rb+gid)*36 + kw + tig+4]; al2[mt][3] = Asl[(rb+gid+8)*36 + kw + tig+4];
        }
#pragma unroll
        for (int nt = 0; nt < 2; nt++) {
            int d = wn * 16 + nt * 8 + gid;
            uint32_t bh2[2] = { g_Vh[vb + d*32 + kw + tig], g_Vh[vb + d*32 + kw + tig + 4] };
            uint32_t bl2[2] = { g_Vl[vb + d*32 + kw + tig], g_Vl[vb + d*32 + kw + tig + 4] };
#pragma unroll
            for (int mt = 0; mt < 2; mt++) {
                mma_bf16(aN[mt][nt], ah[mt],  bh2);
                mma_bf16(aN[mt][nt], ah[mt],  bl2);
                mma_bf16(aN[mt][nt], al2[mt], bh2);
            }
        }
        if (wn == 0) {
#pragma unroll
            for (int mt = 0; mt < 2; mt++) {
                mma_bf16(aD[mt], ah[mt],  ones);
                mma_bf16(aD[mt], al2[mt], ones);
            }
        }
    }
    if (wn == 0 && tig == 0) {
#pragma unroll
        for (int mt = 0; mt < 2; mt++) {
            den[wm * 32 + mt * 16 + gid]     = aD[mt][0];
            den[wm * 32 + mt * 16 + gid + 8] = aD[mt][2];
        }
    }
    __syncthreads();

    // divide & store
#pragma unroll
    for (int mt = 0; mt < 2; mt++) {
        int ri0 = wm * 32 + mt * 16 + gid, ri1 = ri0 + 8;
        float inv0 = 1.0f / (den[ri0] + 1e-12f);
        float inv1 = 1.0f / (den[ri1] + 1e-12f);
#pragma unroll
        for (int nt = 0; nt < 2; nt++) {
            int cb0 = wn * 16 + nt * 8 + tig * 2;
            *(float2*)&g_Y[(c * CH + ri0) * DM + h * HD + cb0] =
                make_float2(aN[mt][nt][0] * inv0, aN[mt][nt][1] * inv0);
            *(float2*)&g_Y[(c * CH + ri1) * DM + h * HD + cb0] =
                make_float2(aN[mt][nt][2] * inv1, aN[mt][nt][3] * inv1);
        }
    }
}

// ---------------------------------------------------------------------------
extern "C" void kernel_launch(void* const* d_in, const int* in_sizes, int n_in,
                              void* d_out, int out_size) {
    const float* hs = (const float*)d_in[0];
    const float* Wq = (const float*)d_in[1];
    const float* Wk = (const float*)d_in[2];
    const float* Wv = (const float*)d_in[3];
    const float* Wo = (const float*)d_in[4];
    float* out = (float*)d_out;

    cudaFuncSetAttribute(chunk_attn_k, cudaFuncAttributeMaxDynamicSharedMemorySize, ATTN_SMEM);
    cudaFuncSetAttribute(qkv_gemm, cudaFuncAttributeMaxDynamicSharedMemorySize, SMEM_GEMM_BYTES);
    cudaFuncSetAttribute(o_gemm,   cudaFuncAttributeMaxDynamicSharedMemorySize, SMEM_GEMM_BYTES);

    qkv_gemm<<<dim3(18, 16), 128, SMEM_GEMM_BYTES>>>(hs, Wq, Wk, Wv);
    featurize_k<<<dim3(NC, NH, 4), 256>>>();
    chunk_kv_k<<<dim3(2, NC, NH), 288>>>();
    {
        int total = NH * 64 * NW + NH * NW;   // 112320
        prefix_k<<<(total + 255) / 256, 256>>>();
    }
    chunk_attn_k<<<dim3(NC, NH), 256, ATTN_SMEM>>>();
    o_gemm<<<dim3(12, 16), 128, SMEM_GEMM_BYTES>>>(Wo, out);
}